// round 1
// baseline (speedup 1.0000x reference)
#include <cuda_runtime.h>
#include <cuda_bf16.h>
#include <cstdint>
#include <cstddef>
#include <math.h>

// ---------------------------------------------------------------------------
// BartCrossAttention: B=4, LQ=LK=1024, D=1024, H=16, HD=64, fp32
//   Q  = X @ Wq^T + bq            [4096,1024]
//   KV = Y @ Wkv^T + bkv          [4096,2048]  (per head h: K cols h*128..+63, V cols h*128+64..+127)
//   attn: per (b,h): softmax(Q K^T / 8) V  -> ctx [4096,1024]
//   out = ctx @ Wo^T + bo         [4096,1024]
// ---------------------------------------------------------------------------

#define BATCH 4
#define LQ    1024
#define LK    1024
#define DMODEL 1024
#define NHEAD 16
#define HDIM  64

// Scratch (allocation-free rule: __device__ globals)
__device__ float g_q  [(size_t)BATCH * LQ * DMODEL];     // 16 MB
__device__ float g_kv [(size_t)BATCH * LK * 2 * DMODEL]; // 32 MB
__device__ float g_ctx[(size_t)BATCH * LQ * DMODEL];     // 16 MB

// ---------------------------------------------------------------------------
// GEMM: C[M,N] = A[M,K] @ W[N,K]^T + bias[N]
// 128x128 tile, BK=8, 256 threads, 8x8 per thread (split 4+4), float4 everywhere.
// ---------------------------------------------------------------------------
#define GBM 128
#define GBN 128
#define GBK 8

__global__ __launch_bounds__(256) void gemm_bias_kernel(
    const float* __restrict__ A, const float* __restrict__ W,
    const float* __restrict__ bias, float* __restrict__ C,
    int M, int N, int K)
{
    __shared__ float As[GBK][GBM + 4];
    __shared__ float Bs[GBK][GBN + 4];

    const int tid = threadIdx.x;
    const int tx  = tid & 15;      // 0..15 -> N
    const int ty  = tid >> 4;      // 0..15 -> M
    const int lrow = tid >> 1;     // 0..127
    const int lcol = (tid & 1) << 2; // 0 or 4

    const float* Ab = A + (size_t)blockIdx.y * GBM * K + (size_t)lrow * K + lcol;
    const float* Wb = W + (size_t)blockIdx.x * GBN * K + (size_t)lrow * K + lcol;

    float acc[8][8];
#pragma unroll
    for (int i = 0; i < 8; i++)
#pragma unroll
        for (int j = 0; j < 8; j++) acc[i][j] = 0.f;

    for (int k0 = 0; k0 < K; k0 += GBK) {
        float4 a = *(const float4*)(Ab + k0);
        float4 b = *(const float4*)(Wb + k0);
        As[lcol + 0][lrow] = a.x; As[lcol + 1][lrow] = a.y;
        As[lcol + 2][lrow] = a.z; As[lcol + 3][lrow] = a.w;
        Bs[lcol + 0][lrow] = b.x; Bs[lcol + 1][lrow] = b.y;
        Bs[lcol + 2][lrow] = b.z; Bs[lcol + 3][lrow] = b.w;
        __syncthreads();

#pragma unroll
        for (int k = 0; k < GBK; k++) {
            float ar[8], br[8];
            *(float4*)&ar[0] = *(const float4*)&As[k][ty * 4];
            *(float4*)&ar[4] = *(const float4*)&As[k][ty * 4 + 64];
            *(float4*)&br[0] = *(const float4*)&Bs[k][tx * 4];
            *(float4*)&br[4] = *(const float4*)&Bs[k][tx * 4 + 64];
#pragma unroll
            for (int i = 0; i < 8; i++)
#pragma unroll
                for (int j = 0; j < 8; j++)
                    acc[i][j] = fmaf(ar[i], br[j], acc[i][j]);
        }
        __syncthreads();
    }

#pragma unroll
    for (int i = 0; i < 8; i++) {
        int m = blockIdx.y * GBM + ((i < 4) ? (ty * 4 + i) : (64 + ty * 4 + i - 4));
#pragma unroll
        for (int jj = 0; jj < 2; jj++) {
            int n = blockIdx.x * GBN + ((jj == 0) ? (tx * 4) : (64 + tx * 4));
            float4 o;
            o.x = acc[i][jj * 4 + 0] + bias[n + 0];
            o.y = acc[i][jj * 4 + 1] + bias[n + 1];
            o.z = acc[i][jj * 4 + 2] + bias[n + 2];
            o.w = acc[i][jj * 4 + 3] + bias[n + 3];
            *(float4*)(C + (size_t)m * N + n) = o;
        }
    }
}

// ---------------------------------------------------------------------------
// Flash attention: grid (LQ/64, H, B), 256 threads.
// Q and K stored d-major (transposed) in smem so the S inner loop is
// float4 broadcast (Q) + float4 stream (K). V row-major for the PV float4 loads.
// Online softmax with per-row (m, l) in registers of threads 0..63.
// Dynamic smem: 4 * 64*68 floats + 2*64 = 70144 B.
// ---------------------------------------------------------------------------
#define ATT_PAD 68
#define ATT_SMEM_FLOATS (4 * 64 * ATT_PAD + 2 * 64)
#define ATT_SMEM_BYTES  (ATT_SMEM_FLOATS * 4)

__global__ __launch_bounds__(256) void attn_kernel(
    const float* __restrict__ Q, const float* __restrict__ KV,
    float* __restrict__ Ctx)
{
    extern __shared__ float sm[];
    float* Qt     = sm;                    // [64 d][68]  (d-major)
    float* Kt     = Qt + 64 * ATT_PAD;     // [64 d][68]  (d-major)
    float* Vs     = Kt + 64 * ATT_PAD;     // [64 j][68]  (row-major)
    float* Ss     = Vs + 64 * ATT_PAD;     // [64 q][68]
    float* corr_s = Ss + 64 * ATT_PAD;     // [64]
    float* l_s    = corr_s + 64;           // [64]

    const int tid = threadIdx.x;
    const int tx  = tid & 15;   // cols (HD or K-tile)
    const int ty  = tid >> 4;   // rows (Q)
    const int qt  = blockIdx.x;
    const int h   = blockIdx.y;
    const int b   = blockIdx.z;
    const float scale = 0.125f; // 1/sqrt(64)

    const float* Qg  = Q  + ((size_t)(b * LQ + qt * 64)) * DMODEL + h * HDIM;
    const float* KVg = KV + (size_t)b * LK * (2 * DMODEL) + h * (2 * HDIM);

    // Load Q tile transposed: Qt[d][r] = Q[r][d]
#pragma unroll
    for (int it = 0; it < 4; it++) {
        int idx = it * 256 + tid;        // 0..1023
        int r   = idx >> 4;              // 0..63
        int c4  = (idx & 15) << 2;       // 0,4,..,60
        float4 v = *(const float4*)(Qg + (size_t)r * DMODEL + c4);
        Qt[(c4 + 0) * ATT_PAD + r] = v.x;
        Qt[(c4 + 1) * ATT_PAD + r] = v.y;
        Qt[(c4 + 2) * ATT_PAD + r] = v.z;
        Qt[(c4 + 3) * ATT_PAD + r] = v.w;
    }

    float o[4][4];
#pragma unroll
    for (int i = 0; i < 4; i++)
#pragma unroll
        for (int j = 0; j < 4; j++) o[i][j] = 0.f;

    float mReg = -INFINITY, lReg = 0.f;

    for (int kt = 0; kt < LK / 64; kt++) {
        const float* Kb = KVg + (size_t)(kt * 64) * (2 * DMODEL);
        // Load K (transposed) and V (row-major)
#pragma unroll
        for (int it = 0; it < 4; it++) {
            int idx = it * 256 + tid;
            int r   = idx >> 4;
            int c4  = (idx & 15) << 2;
            float4 kv = *(const float4*)(Kb + (size_t)r * (2 * DMODEL) + c4);
            Kt[(c4 + 0) * ATT_PAD + r] = kv.x;
            Kt[(c4 + 1) * ATT_PAD + r] = kv.y;
            Kt[(c4 + 2) * ATT_PAD + r] = kv.z;
            Kt[(c4 + 3) * ATT_PAD + r] = kv.w;
            float4 vv = *(const float4*)(Kb + (size_t)r * (2 * DMODEL) + HDIM + c4);
            *(float4*)&Vs[r * ATT_PAD + c4] = vv;
        }
        __syncthreads();

        // S[4][4] = Q K^T for rows ty*4.., cols tx*4..
        float s[4][4];
#pragma unroll
        for (int i = 0; i < 4; i++)
#pragma unroll
            for (int j = 0; j < 4; j++) s[i][j] = 0.f;

#pragma unroll 8
        for (int d = 0; d < HDIM; d++) {
            float4 q = *(const float4*)&Qt[d * ATT_PAD + ty * 4];
            float4 k = *(const float4*)&Kt[d * ATT_PAD + tx * 4];
            float qa[4] = {q.x, q.y, q.z, q.w};
            float ka[4] = {k.x, k.y, k.z, k.w};
#pragma unroll
            for (int i = 0; i < 4; i++)
#pragma unroll
                for (int j = 0; j < 4; j++)
                    s[i][j] = fmaf(qa[i], ka[j], s[i][j]);
        }

        // Write scaled S to smem
#pragma unroll
        for (int i = 0; i < 4; i++) {
            float4 sv;
            sv.x = s[i][0] * scale; sv.y = s[i][1] * scale;
            sv.z = s[i][2] * scale; sv.w = s[i][3] * scale;
            *(float4*)&Ss[(ty * 4 + i) * ATT_PAD + tx * 4] = sv;
        }
        __syncthreads();

        // Online softmax: one thread per row
        if (tid < 64) {
            float* row = Ss + tid * ATT_PAD;
            float mNew = mReg;
#pragma unroll 16
            for (int j = 0; j < 64; j++) mNew = fmaxf(mNew, row[j]);
            float c = __expf(mReg - mNew);
            float sum = 0.f;
#pragma unroll 16
            for (int j = 0; j < 64; j++) {
                float p = __expf(row[j] - mNew);
                row[j] = p;
                sum += p;
            }
            lReg = lReg * c + sum;
            mReg = mNew;
            corr_s[tid] = c;
        }
        __syncthreads();

        // Rescale accumulators and add P @ V
        float cr[4];
#pragma unroll
        for (int i = 0; i < 4; i++) cr[i] = corr_s[ty * 4 + i];
#pragma unroll
        for (int i = 0; i < 4; i++)
#pragma unroll
            for (int j = 0; j < 4; j++) o[i][j] *= cr[i];

#pragma unroll 8
        for (int jj = 0; jj < 64; jj++) {
            float4 v = *(const float4*)&Vs[jj * ATT_PAD + tx * 4];
            float va[4] = {v.x, v.y, v.z, v.w};
            float p0 = Ss[(ty * 4 + 0) * ATT_PAD + jj];
            float p1 = Ss[(ty * 4 + 1) * ATT_PAD + jj];
            float p2 = Ss[(ty * 4 + 2) * ATT_PAD + jj];
            float p3 = Ss[(ty * 4 + 3) * ATT_PAD + jj];
#pragma unroll
            for (int j = 0; j < 4; j++) {
                o[0][j] = fmaf(p0, va[j], o[0][j]);
                o[1][j] = fmaf(p1, va[j], o[1][j]);
                o[2][j] = fmaf(p2, va[j], o[2][j]);
                o[3][j] = fmaf(p3, va[j], o[3][j]);
            }
        }
        __syncthreads();  // protect Kt/Vs/Ss/corr_s for next tile
    }

    if (tid < 64) l_s[tid] = lReg;
    __syncthreads();

#pragma unroll
    for (int i = 0; i < 4; i++) {
        int r = ty * 4 + i;
        float inv = 1.f / l_s[r];
        float4 ov;
        ov.x = o[i][0] * inv; ov.y = o[i][1] * inv;
        ov.z = o[i][2] * inv; ov.w = o[i][3] * inv;
        *(float4*)(Ctx + ((size_t)(b * LQ + qt * 64 + r)) * DMODEL + h * HDIM + tx * 4) = ov;
    }
}

// ---------------------------------------------------------------------------
// Launch
// ---------------------------------------------------------------------------
extern "C" void kernel_launch(void* const* d_in, const int* in_sizes, int n_in,
                              void* d_out, int out_size)
{
    const float* X   = (const float*)d_in[0];  // hidden_states   [4,1024,1024]
    const float* Y   = (const float*)d_in[1];  // key_value_states[4,1024,1024]
    const float* Wq  = (const float*)d_in[2];  // [1024,1024]
    const float* bq  = (const float*)d_in[3];  // [1024]
    const float* Wkv = (const float*)d_in[4];  // [2048,1024]
    const float* bkv = (const float*)d_in[5];  // [2048]
    const float* Wo  = (const float*)d_in[6];  // [1024,1024]
    const float* bo  = (const float*)d_in[7];  // [1024]
    float* out = (float*)d_out;

    void *pq = nullptr, *pkv = nullptr, *pctx = nullptr;
    cudaGetSymbolAddress(&pq,  g_q);
    cudaGetSymbolAddress(&pkv, g_kv);
    cudaGetSymbolAddress(&pctx, g_ctx);
    float* q_s   = (float*)pq;
    float* kv_s  = (float*)pkv;
    float* ctx_s = (float*)pctx;

    cudaFuncSetAttribute(attn_kernel, cudaFuncAttributeMaxDynamicSharedMemorySize,
                         ATT_SMEM_BYTES);

    const int M = BATCH * LQ;  // 4096

    // 1) Q projection
    gemm_bias_kernel<<<dim3(DMODEL / GBN, M / GBM), 256>>>(X, Wq, bq, q_s,
                                                           M, DMODEL, DMODEL);
    // 2) KV projection
    gemm_bias_kernel<<<dim3(2 * DMODEL / GBN, M / GBM), 256>>>(Y, Wkv, bkv, kv_s,
                                                               M, 2 * DMODEL, DMODEL);
    // 3) Attention
    attn_kernel<<<dim3(LQ / 64, NHEAD, BATCH), 256, ATT_SMEM_BYTES>>>(q_s, kv_s, ctx_s);

    // 4) Output projection
    gemm_bias_kernel<<<dim3(DMODEL / GBN, M / GBM), 256>>>(ctx_s, Wo, bo, out,
                                                           M, DMODEL, DMODEL);
}

// round 3
// speedup vs baseline: 1.7260x; 1.7260x over previous
#include <cuda_runtime.h>
#include <cuda_bf16.h>
#include <cstdint>
#include <cstddef>
#include <math.h>

// ---------------------------------------------------------------------------
// BartCrossAttention: B=4, LQ=LK=1024, D=1024, H=16, HD=64, fp32 in/out
// Round 3: projections via warp-level mma.sync tf32 (compute_100-safe),
//          attention kept as fp32 SIMT flash kernel.
// ---------------------------------------------------------------------------

#define BATCH 4
#define LQ    1024
#define LK    1024
#define DMODEL 1024
#define NHEAD 16
#define HDIM  64

// Scratch (__device__ globals; no allocations allowed)
__device__ float g_xr  [(size_t)BATCH * LQ * DMODEL];      // X rounded to tf32
__device__ float g_yr  [(size_t)BATCH * LK * DMODEL];      // Y rounded
__device__ float g_wqr [(size_t)DMODEL * DMODEL];          // Wq rounded
__device__ float g_wkvr[(size_t)2 * DMODEL * DMODEL];      // Wkv rounded
__device__ float g_wor [(size_t)DMODEL * DMODEL];          // Wo rounded
__device__ float g_q   [(size_t)BATCH * LQ * DMODEL];
__device__ float g_kv  [(size_t)BATCH * LK * 2 * DMODEL];
__device__ float g_ctx [(size_t)BATCH * LQ * DMODEL];      // tf32-rounded ctx

// ---------------------------------------------------------------------------
// helpers
// ---------------------------------------------------------------------------
__device__ __forceinline__ uint32_t smem_u32(const void* p) {
    uint32_t a;
    asm("{ .reg .u64 t; cvta.to.shared.u64 t, %1; cvt.u32.u64 %0, t; }"
        : "=r"(a) : "l"(p));
    return a;
}

__device__ __forceinline__ float round_tf32(float x) {
    uint32_t r;
    asm("cvt.rna.tf32.f32 %0, %1;" : "=r"(r) : "f"(x));
    return __uint_as_float(r);
}

// m16n8k8 tf32 mma: c[4] += a[4] * b[2]
__device__ __forceinline__ void mma_tf32(float* c, const float* a, const float* b) {
    const uint32_t* A = reinterpret_cast<const uint32_t*>(a);
    const uint32_t* B = reinterpret_cast<const uint32_t*>(b);
    asm volatile(
        "mma.sync.aligned.m16n8k8.row.col.f32.tf32.tf32.f32 "
        "{%0,%1,%2,%3}, {%4,%5,%6,%7}, {%8,%9}, {%0,%1,%2,%3};"
        : "+f"(c[0]), "+f"(c[1]), "+f"(c[2]), "+f"(c[3])
        : "r"(A[0]), "r"(A[1]), "r"(A[2]), "r"(A[3]), "r"(B[0]), "r"(B[1]));
}

__device__ __forceinline__ void cp_async16(uint32_t dst, const void* src) {
    asm volatile("cp.async.cg.shared.global [%0], [%1], 16;"
                 :: "r"(dst), "l"(src));
}
#define CP_COMMIT()  asm volatile("cp.async.commit_group;" ::: "memory")
#define CP_WAIT(n)   asm volatile("cp.async.wait_group %0;" :: "n"(n) : "memory")

// ---------------------------------------------------------------------------
// tf32 tensor-core GEMM: C[M,N] = A[M,K] @ W[N,K]^T + bias[N]
// Block 128x128, 8 warps (2x4), warp tile 64x32, BK=32, 3-stage cp.async.
// Inputs must already be RNA-rounded to tf32.
// ---------------------------------------------------------------------------
#define BM 128
#define BN 128
#define BK 32
#define GSTAGES 3
#define ASTR 36                               // smem row stride in floats (144B)
#define STG_FLOATS ((BM + BN) * ASTR)         // 9216 floats
#define STG_BYTES  (STG_FLOATS * 4)           // 36864 B
#define GEMM_SMEM  (GSTAGES * STG_BYTES)      // 110592 B

__global__ __launch_bounds__(256, 2) void gemm_tf32(
    const float* __restrict__ A, const float* __restrict__ W,
    const float* __restrict__ bias, float* __restrict__ C,
    int M, int N, int K)
{
    extern __shared__ float sm[];
    const uint32_t sbase = smem_u32(sm);

    const int tid  = threadIdx.x;
    const int wid  = tid >> 5;
    const int lane = tid & 31;
    const int g    = lane >> 2;     // 0..7
    const int tg   = lane & 3;      // 0..3
    const int wm   = (wid & 1) * 64;
    const int wn   = (wid >> 1) * 32;
    const int m0   = blockIdx.y * BM;
    const int n0   = blockIdx.x * BN;

    // cp.async assignment: 2048 16B chunks per stage (A:1024, B:1024), 8/thread
    auto load_stage = [&](int chunk, int s) {
        const int k0 = chunk * BK;
        const uint32_t stA = sbase + s * STG_BYTES;
        const uint32_t stB = stA + BM * ASTR * 4;
#pragma unroll
        for (int i = 0; i < 8; i++) {
            int idx = i * 256 + tid;
            if (idx < 1024) {
                int row = idx >> 3, c16 = idx & 7;
                cp_async16(stA + row * (ASTR * 4) + c16 * 16,
                           A + (size_t)(m0 + row) * K + k0 + c16 * 4);
            } else {
                int j = idx - 1024;
                int row = j >> 3, c16 = j & 7;
                cp_async16(stB + row * (ASTR * 4) + c16 * 16,
                           W + (size_t)(n0 + row) * K + k0 + c16 * 4);
            }
        }
    };

    float acc[4][4][4];
#pragma unroll
    for (int mi = 0; mi < 4; mi++)
#pragma unroll
        for (int ni = 0; ni < 4; ni++)
#pragma unroll
            for (int r = 0; r < 4; r++) acc[mi][ni][r] = 0.f;

    const int nchunks = K / BK;

    load_stage(0, 0); CP_COMMIT();
    load_stage(1, 1); CP_COMMIT();

    for (int k = 0; k < nchunks; k++) {
        const int s = k % GSTAGES;
        if (k + 2 < nchunks) load_stage(k + 2, (k + 2) % GSTAGES);
        CP_COMMIT();                 // always commit (possibly empty group)
        CP_WAIT(2);                  // chunk k resident
        __syncthreads();

        const float* as = sm + s * STG_FLOATS;
        const float* bs = as + BM * ASTR;

#pragma unroll
        for (int ks = 0; ks < BK / 8; ks++) {
            const int kc = ks * 8 + tg;
            float af[4][4];
#pragma unroll
            for (int mi = 0; mi < 4; mi++) {
                const float* p = as + (wm + mi * 16 + g) * ASTR + kc;
                af[mi][0] = p[0];
                af[mi][1] = p[8 * ASTR];
                af[mi][2] = p[4];
                af[mi][3] = p[8 * ASTR + 4];
            }
            float bf[4][2];
#pragma unroll
            for (int ni = 0; ni < 4; ni++) {
                const float* p = bs + (wn + ni * 8 + g) * ASTR + kc;
                bf[ni][0] = p[0];
                bf[ni][1] = p[4];
            }
#pragma unroll
            for (int mi = 0; mi < 4; mi++)
#pragma unroll
                for (int ni = 0; ni < 4; ni++)
                    mma_tf32(acc[mi][ni], af[mi], bf[ni]);
        }
        __syncthreads();
    }

    // epilogue: bias + store (float2 per half-fragment)
#pragma unroll
    for (int ni = 0; ni < 4; ni++) {
        const int col = n0 + wn + ni * 8 + 2 * tg;
        const float2 bv = *(const float2*)(bias + col);
#pragma unroll
        for (int mi = 0; mi < 4; mi++) {
            const int r0 = m0 + wm + mi * 16 + g;
            float2 v0 = { acc[mi][ni][0] + bv.x, acc[mi][ni][1] + bv.y };
            float2 v1 = { acc[mi][ni][2] + bv.x, acc[mi][ni][3] + bv.y };
            *(float2*)(C + (size_t)r0 * N + col) = v0;
            *(float2*)(C + (size_t)(r0 + 8) * N + col) = v1;
        }
    }
}

// ---------------------------------------------------------------------------
// Elementwise RNA round-to-tf32 convert (float4 vectorized)
// ---------------------------------------------------------------------------
__global__ __launch_bounds__(256) void cvt_tf32_kernel(
    const float* __restrict__ in, float* __restrict__ out, int n4)
{
    int i = blockIdx.x * blockDim.x + threadIdx.x;
    if (i < n4) {
        float4 v = ((const float4*)in)[i];
        v.x = round_tf32(v.x); v.y = round_tf32(v.y);
        v.z = round_tf32(v.z); v.w = round_tf32(v.w);
        ((float4*)out)[i] = v;
    }
}

// ---------------------------------------------------------------------------
// Flash attention (fp32 SIMT; epilogue writes tf32-rounded ctx)
// ---------------------------------------------------------------------------
#define ATT_PAD 68
#define ATT_SMEM_FLOATS (4 * 64 * ATT_PAD + 2 * 64)
#define ATT_SMEM_BYTES  (ATT_SMEM_FLOATS * 4)

__global__ __launch_bounds__(256) void attn_kernel(
    const float* __restrict__ Q, const float* __restrict__ KV,
    float* __restrict__ Ctx)
{
    extern __shared__ float smf[];
    float* Qt     = smf;
    float* Kt     = Qt + 64 * ATT_PAD;
    float* Vs     = Kt + 64 * ATT_PAD;
    float* Ss     = Vs + 64 * ATT_PAD;
    float* corr_s = Ss + 64 * ATT_PAD;
    float* l_s    = corr_s + 64;

    const int tid = threadIdx.x;
    const int tx  = tid & 15;
    const int ty  = tid >> 4;
    const int qt  = blockIdx.x;
    const int h   = blockIdx.y;
    const int b   = blockIdx.z;
    const float scale = 0.125f;

    const float* Qg  = Q  + ((size_t)(b * LQ + qt * 64)) * DMODEL + h * HDIM;
    const float* KVg = KV + (size_t)b * LK * (2 * DMODEL) + h * (2 * HDIM);

#pragma unroll
    for (int it = 0; it < 4; it++) {
        int idx = it * 256 + tid;
        int r   = idx >> 4;
        int c4  = (idx & 15) << 2;
        float4 v = *(const float4*)(Qg + (size_t)r * DMODEL + c4);
        Qt[(c4 + 0) * ATT_PAD + r] = v.x;
        Qt[(c4 + 1) * ATT_PAD + r] = v.y;
        Qt[(c4 + 2) * ATT_PAD + r] = v.z;
        Qt[(c4 + 3) * ATT_PAD + r] = v.w;
    }

    float o[4][4];
#pragma unroll
    for (int i = 0; i < 4; i++)
#pragma unroll
        for (int j = 0; j < 4; j++) o[i][j] = 0.f;

    float mReg = -INFINITY, lReg = 0.f;

    for (int kt = 0; kt < LK / 64; kt++) {
        const float* Kb = KVg + (size_t)(kt * 64) * (2 * DMODEL);
#pragma unroll
        for (int it = 0; it < 4; it++) {
            int idx = it * 256 + tid;
            int r   = idx >> 4;
            int c4  = (idx & 15) << 2;
            float4 kv = *(const float4*)(Kb + (size_t)r * (2 * DMODEL) + c4);
            Kt[(c4 + 0) * ATT_PAD + r] = kv.x;
            Kt[(c4 + 1) * ATT_PAD + r] = kv.y;
            Kt[(c4 + 2) * ATT_PAD + r] = kv.z;
            Kt[(c4 + 3) * ATT_PAD + r] = kv.w;
            float4 vv = *(const float4*)(Kb + (size_t)r * (2 * DMODEL) + HDIM + c4);
            *(float4*)&Vs[r * ATT_PAD + c4] = vv;
        }
        __syncthreads();

        float s[4][4];
#pragma unroll
        for (int i = 0; i < 4; i++)
#pragma unroll
            for (int j = 0; j < 4; j++) s[i][j] = 0.f;

#pragma unroll 8
        for (int d = 0; d < HDIM; d++) {
            float4 q = *(const float4*)&Qt[d * ATT_PAD + ty * 4];
            float4 k = *(const float4*)&Kt[d * ATT_PAD + tx * 4];
            float qa[4] = {q.x, q.y, q.z, q.w};
            float ka[4] = {k.x, k.y, k.z, k.w};
#pragma unroll
            for (int i = 0; i < 4; i++)
#pragma unroll
                for (int j = 0; j < 4; j++)
                    s[i][j] = fmaf(qa[i], ka[j], s[i][j]);
        }

#pragma unroll
        for (int i = 0; i < 4; i++) {
            float4 sv;
            sv.x = s[i][0] * scale; sv.y = s[i][1] * scale;
            sv.z = s[i][2] * scale; sv.w = s[i][3] * scale;
            *(float4*)&Ss[(ty * 4 + i) * ATT_PAD + tx * 4] = sv;
        }
        __syncthreads();

        if (tid < 64) {
            float* row = Ss + tid * ATT_PAD;
            float mNew = mReg;
#pragma unroll 16
            for (int j = 0; j < 64; j++) mNew = fmaxf(mNew, row[j]);
            float c = __expf(mReg - mNew);
            float sum = 0.f;
#pragma unroll 16
            for (int j = 0; j < 64; j++) {
                float p = __expf(row[j] - mNew);
                row[j] = p;
                sum += p;
            }
            lReg = lReg * c + sum;
            mReg = mNew;
            corr_s[tid] = c;
        }
        __syncthreads();

        float cr[4];
#pragma unroll
        for (int i = 0; i < 4; i++) cr[i] = corr_s[ty * 4 + i];
#pragma unroll
        for (int i = 0; i < 4; i++)
#pragma unroll
            for (int j = 0; j < 4; j++) o[i][j] *= cr[i];

#pragma unroll 8
        for (int jj = 0; jj < 64; jj++) {
            float4 v = *(const float4*)&Vs[jj * ATT_PAD + tx * 4];
            float va[4] = {v.x, v.y, v.z, v.w};
            float p0 = Ss[(ty * 4 + 0) * ATT_PAD + jj];
            float p1 = Ss[(ty * 4 + 1) * ATT_PAD + jj];
            float p2 = Ss[(ty * 4 + 2) * ATT_PAD + jj];
            float p3 = Ss[(ty * 4 + 3) * ATT_PAD + jj];
#pragma unroll
            for (int j = 0; j < 4; j++) {
                o[0][j] = fmaf(p0, va[j], o[0][j]);
                o[1][j] = fmaf(p1, va[j], o[1][j]);
                o[2][j] = fmaf(p2, va[j], o[2][j]);
                o[3][j] = fmaf(p3, va[j], o[3][j]);
            }
        }
        __syncthreads();
    }

    if (tid < 64) l_s[tid] = lReg;
    __syncthreads();

#pragma unroll
    for (int i = 0; i < 4; i++) {
        int r = ty * 4 + i;
        float inv = 1.f / l_s[r];
        float4 ov;
        ov.x = round_tf32(o[i][0] * inv);
        ov.y = round_tf32(o[i][1] * inv);
        ov.z = round_tf32(o[i][2] * inv);
        ov.w = round_tf32(o[i][3] * inv);
        *(float4*)(Ctx + ((size_t)(b * LQ + qt * 64 + r)) * DMODEL + h * HDIM + tx * 4) = ov;
    }
}

// ---------------------------------------------------------------------------
// Launch
// ---------------------------------------------------------------------------
extern "C" void kernel_launch(void* const* d_in, const int* in_sizes, int n_in,
                              void* d_out, int out_size)
{
    const float* X   = (const float*)d_in[0];
    const float* Y   = (const float*)d_in[1];
    const float* Wq  = (const float*)d_in[2];
    const float* bq  = (const float*)d_in[3];
    const float* Wkv = (const float*)d_in[4];
    const float* bkv = (const float*)d_in[5];
    const float* Wo  = (const float*)d_in[6];
    const float* bo  = (const float*)d_in[7];
    float* out = (float*)d_out;

    void *pxr, *pyr, *pwq, *pwkv, *pwo, *pq, *pkv, *pctx;
    cudaGetSymbolAddress(&pxr,  g_xr);
    cudaGetSymbolAddress(&pyr,  g_yr);
    cudaGetSymbolAddress(&pwq,  g_wqr);
    cudaGetSymbolAddress(&pwkv, g_wkvr);
    cudaGetSymbolAddress(&pwo,  g_wor);
    cudaGetSymbolAddress(&pq,   g_q);
    cudaGetSymbolAddress(&pkv,  g_kv);
    cudaGetSymbolAddress(&pctx, g_ctx);
    float* xr   = (float*)pxr;   float* yr   = (float*)pyr;
    float* wqr  = (float*)pwq;   float* wkvr = (float*)pwkv;
    float* wor  = (float*)pwo;
    float* q_s  = (float*)pq;    float* kv_s = (float*)pkv;
    float* ctx_s = (float*)pctx;

    cudaFuncSetAttribute(gemm_tf32, cudaFuncAttributeMaxDynamicSharedMemorySize,
                         GEMM_SMEM);
    cudaFuncSetAttribute(attn_kernel, cudaFuncAttributeMaxDynamicSharedMemorySize,
                         ATT_SMEM_BYTES);

    const int M = BATCH * LQ;  // 4096

    // 0) RNA-round GEMM operands to tf32
    auto cvt = [&](const float* in, float* o, int n) {
        int n4 = n / 4;
        cvt_tf32_kernel<<<(n4 + 255) / 256, 256>>>(in, o, n4);
    };
    cvt(X,   xr,   M * DMODEL);
    cvt(Y,   yr,   M * DMODEL);
    cvt(Wq,  wqr,  DMODEL * DMODEL);
    cvt(Wkv, wkvr, 2 * DMODEL * DMODEL);
    cvt(Wo,  wor,  DMODEL * DMODEL);

    // 1) Q projection
    gemm_tf32<<<dim3(DMODEL / BN, M / BM), 256, GEMM_SMEM>>>(
        xr, wqr, bq, q_s, M, DMODEL, DMODEL);
    // 2) KV projection
    gemm_tf32<<<dim3(2 * DMODEL / BN, M / BM), 256, GEMM_SMEM>>>(
        yr, wkvr, bkv, kv_s, M, 2 * DMODEL, DMODEL);
    // 3) Attention
    attn_kernel<<<dim3(LQ / 64, NHEAD, BATCH), 256, ATT_SMEM_BYTES>>>(q_s, kv_s, ctx_s);
    // 4) Output projection
    gemm_tf32<<<dim3(DMODEL / BN, M / BM), 256, GEMM_SMEM>>>(
        ctx_s, wor, bo, out, M, DMODEL, DMODEL);
}

// round 4
// speedup vs baseline: 3.7179x; 2.1541x over previous
#include <cuda_runtime.h>
#include <cuda_fp16.h>
#include <cuda_bf16.h>
#include <cstdint>
#include <cstddef>
#include <math.h>

// ---------------------------------------------------------------------------
// BartCrossAttention: B=4, LQ=LK=1024, D=1024, H=16, HD=64, fp32 in/out
// Round 4: tf32 mma projections + fp16 mma flash attention (FA-2 style).
// ---------------------------------------------------------------------------

#define BATCH 4
#define LQ    1024
#define LK    1024
#define DMODEL 1024
#define NHEAD 16
#define HDIM  64

// Scratch (__device__ globals; no allocations allowed)
__device__ float  g_xr  [(size_t)BATCH * LQ * DMODEL];
__device__ float  g_yr  [(size_t)BATCH * LK * DMODEL];
__device__ float  g_wqr [(size_t)DMODEL * DMODEL];
__device__ float  g_wkvr[(size_t)2 * DMODEL * DMODEL];
__device__ float  g_wor [(size_t)DMODEL * DMODEL];
__device__ __half g_qh  [(size_t)BATCH * LQ * DMODEL];            // Q fp16 [tok][1024]
__device__ __half g_kh  [(size_t)BATCH * LK * DMODEL];            // K fp16 [tok][h*64+d]
__device__ __half g_vth [(size_t)BATCH * NHEAD * HDIM * LK];      // V^T fp16 [(b,h,d)][tok]
__device__ float  g_ctx [(size_t)BATCH * LQ * DMODEL];            // tf32-rounded ctx

// ---------------------------------------------------------------------------
// helpers
// ---------------------------------------------------------------------------
__device__ __forceinline__ uint32_t smem_u32(const void* p) {
    uint32_t a;
    asm("{ .reg .u64 t; cvta.to.shared.u64 t, %1; cvt.u32.u64 %0, t; }"
        : "=r"(a) : "l"(p));
    return a;
}

__device__ __forceinline__ float round_tf32(float x) {
    uint32_t r;
    asm("cvt.rna.tf32.f32 %0, %1;" : "=r"(r) : "f"(x));
    return __uint_as_float(r);
}

// m16n8k8 tf32 mma
__device__ __forceinline__ void mma_tf32(float* c, const float* a, const float* b) {
    const uint32_t* A = reinterpret_cast<const uint32_t*>(a);
    const uint32_t* B = reinterpret_cast<const uint32_t*>(b);
    asm volatile(
        "mma.sync.aligned.m16n8k8.row.col.f32.tf32.tf32.f32 "
        "{%0,%1,%2,%3}, {%4,%5,%6,%7}, {%8,%9}, {%0,%1,%2,%3};"
        : "+f"(c[0]), "+f"(c[1]), "+f"(c[2]), "+f"(c[3])
        : "r"(A[0]), "r"(A[1]), "r"(A[2]), "r"(A[3]), "r"(B[0]), "r"(B[1]));
}

// m16n8k16 fp16 mma, fp32 accumulate
__device__ __forceinline__ void mma_f16(float* c, const uint32_t* a, uint32_t b0, uint32_t b1) {
    asm volatile(
        "mma.sync.aligned.m16n8k16.row.col.f32.f16.f16.f32 "
        "{%0,%1,%2,%3}, {%4,%5,%6,%7}, {%8,%9}, {%0,%1,%2,%3};"
        : "+f"(c[0]), "+f"(c[1]), "+f"(c[2]), "+f"(c[3])
        : "r"(a[0]), "r"(a[1]), "r"(a[2]), "r"(a[3]), "r"(b0), "r"(b1));
}

__device__ __forceinline__ void cp_async16(uint32_t dst, const void* src) {
    asm volatile("cp.async.cg.shared.global [%0], [%1], 16;"
                 :: "r"(dst), "l"(src));
}
#define CP_COMMIT()  asm volatile("cp.async.commit_group;" ::: "memory")
#define CP_WAIT(n)   asm volatile("cp.async.wait_group %0;" :: "n"(n) : "memory")

__device__ __forceinline__ uint32_t pack_h2(float lo, float hi) {
    __half2 h = __floats2half2_rn(lo, hi);
    return *reinterpret_cast<uint32_t*>(&h);
}

// ---------------------------------------------------------------------------
// tf32 tensor-core GEMM: C[M,N] = A[M,K] @ W[N,K]^T + bias[N]
// mode 0: fp32 C.  mode 1: fp16 out to Hout ([M][N]).  mode 2: KV split
//   (K half -> Kh [tok][h*64+d], V half -> Vth [(b,h,d)][tok]).
// ---------------------------------------------------------------------------
#define BM 128
#define BN 128
#define BK 32
#define GSTAGES 3
#define ASTR 36
#define STG_FLOATS ((BM + BN) * ASTR)
#define STG_BYTES  (STG_FLOATS * 4)
#define GEMM_SMEM  (GSTAGES * STG_BYTES)

__global__ __launch_bounds__(256, 2) void gemm_tf32(
    const float* __restrict__ A, const float* __restrict__ W,
    const float* __restrict__ bias, float* __restrict__ C,
    __half* __restrict__ Hout, __half* __restrict__ Vth,
    int M, int N, int K, int mode)
{
    extern __shared__ float sm[];
    const uint32_t sbase = smem_u32(sm);

    const int tid  = threadIdx.x;
    const int wid  = tid >> 5;
    const int lane = tid & 31;
    const int g    = lane >> 2;
    const int tg   = lane & 3;
    const int wm   = (wid & 1) * 64;
    const int wn   = (wid >> 1) * 32;
    const int m0   = blockIdx.y * BM;
    const int n0   = blockIdx.x * BN;

    auto load_stage = [&](int chunk, int s) {
        const int k0 = chunk * BK;
        const uint32_t stA = sbase + s * STG_BYTES;
        const uint32_t stB = stA + BM * ASTR * 4;
#pragma unroll
        for (int i = 0; i < 8; i++) {
            int idx = i * 256 + tid;
            if (idx < 1024) {
                int row = idx >> 3, c16 = idx & 7;
                cp_async16(stA + row * (ASTR * 4) + c16 * 16,
                           A + (size_t)(m0 + row) * K + k0 + c16 * 4);
            } else {
                int j = idx - 1024;
                int row = j >> 3, c16 = j & 7;
                cp_async16(stB + row * (ASTR * 4) + c16 * 16,
                           W + (size_t)(n0 + row) * K + k0 + c16 * 4);
            }
        }
    };

    float acc[4][4][4];
#pragma unroll
    for (int mi = 0; mi < 4; mi++)
#pragma unroll
        for (int ni = 0; ni < 4; ni++)
#pragma unroll
            for (int r = 0; r < 4; r++) acc[mi][ni][r] = 0.f;

    const int nchunks = K / BK;
    load_stage(0, 0); CP_COMMIT();
    load_stage(1, 1); CP_COMMIT();

    for (int k = 0; k < nchunks; k++) {
        const int s = k % GSTAGES;
        if (k + 2 < nchunks) load_stage(k + 2, (k + 2) % GSTAGES);
        CP_COMMIT();
        CP_WAIT(2);
        __syncthreads();

        const float* as = sm + s * STG_FLOATS;
        const float* bs = as + BM * ASTR;

#pragma unroll
        for (int ks = 0; ks < BK / 8; ks++) {
            const int kc = ks * 8 + tg;
            float af[4][4];
#pragma unroll
            for (int mi = 0; mi < 4; mi++) {
                const float* p = as + (wm + mi * 16 + g) * ASTR + kc;
                af[mi][0] = p[0];
                af[mi][1] = p[8 * ASTR];
                af[mi][2] = p[4];
                af[mi][3] = p[8 * ASTR + 4];
            }
            float bf[4][2];
#pragma unroll
            for (int ni = 0; ni < 4; ni++) {
                const float* p = bs + (wn + ni * 8 + g) * ASTR + kc;
                bf[ni][0] = p[0];
                bf[ni][1] = p[4];
            }
#pragma unroll
            for (int mi = 0; mi < 4; mi++)
#pragma unroll
                for (int ni = 0; ni < 4; ni++)
                    mma_tf32(acc[mi][ni], af[mi], bf[ni]);
        }
        __syncthreads();
    }

    // epilogue
#pragma unroll
    for (int ni = 0; ni < 4; ni++) {
        const int col = n0 + wn + ni * 8 + 2 * tg;
        const float2 bv = *(const float2*)(bias + col);
#pragma unroll
        for (int mi = 0; mi < 4; mi++) {
            const int r0 = m0 + wm + mi * 16 + g;
            float v00 = acc[mi][ni][0] + bv.x, v01 = acc[mi][ni][1] + bv.y;
            float v10 = acc[mi][ni][2] + bv.x, v11 = acc[mi][ni][3] + bv.y;
            if (mode == 0) {
                float2 a0 = { v00, v01 }, a1 = { v10, v11 };
                *(float2*)(C + (size_t)r0 * N + col) = a0;
                *(float2*)(C + (size_t)(r0 + 8) * N + col) = a1;
            } else if (mode == 1) {
                __half2 h0 = __floats2half2_rn(v00, v01);
                __half2 h1 = __floats2half2_rn(v10, v11);
                *(__half2*)(Hout + (size_t)r0 * N + col) = h0;
                *(__half2*)(Hout + (size_t)(r0 + 8) * N + col) = h1;
            } else {
                // KV split: n = col, h = n>>7, w = n&127
                const int h = col >> 7, w = col & 127;
                const int b = r0 >> 10;
                const int tok = r0 & 1023;
                if (w < 64) {
                    // K half -> Kh[tok_global][h*64 + w]
                    __half2 h0 = __floats2half2_rn(v00, v01);
                    __half2 h1 = __floats2half2_rn(v10, v11);
                    *(__half2*)(Hout + (size_t)r0 * DMODEL + h * 64 + w) = h0;
                    *(__half2*)(Hout + (size_t)(r0 + 8) * DMODEL + h * 64 + w) = h1;
                } else {
                    const int d = w - 64;
                    __half* vr0 = Vth + ((size_t)((b * NHEAD + h) * HDIM + d)) * LK;
                    __half* vr1 = Vth + ((size_t)((b * NHEAD + h) * HDIM + d + 1)) * LK;
                    vr0[tok]     = __float2half_rn(v00);
                    vr1[tok]     = __float2half_rn(v01);
                    vr0[tok + 8] = __float2half_rn(v10);
                    vr1[tok + 8] = __float2half_rn(v11);
                }
            }
        }
    }
}

// ---------------------------------------------------------------------------
// RNA round-to-tf32 convert
// ---------------------------------------------------------------------------
__global__ __launch_bounds__(256) void cvt_tf32_kernel(
    const float* __restrict__ in, float* __restrict__ out, int n4)
{
    int i = blockIdx.x * blockDim.x + threadIdx.x;
    if (i < n4) {
        float4 v = ((const float4*)in)[i];
        v.x = round_tf32(v.x); v.y = round_tf32(v.y);
        v.z = round_tf32(v.z); v.w = round_tf32(v.w);
        ((float4*)out)[i] = v;
    }
}

// ---------------------------------------------------------------------------
// fp16 tensor-core flash attention.
// grid (LQ/128, H, B), 256 threads (8 warps, 16 q-rows each).
// KV tiles of 64, cp.async double-buffered. P stays in registers (FA-2).
// smem strides 72 halves -> fragment lds hit bank (4g+tg): conflict-free.
// ---------------------------------------------------------------------------
#define ABKV 64
#define ANT  (LK / ABKV)          // 16
#define HSTR 72                   // halves
#define AQ_HALVES   (128 * HSTR)  // 9216
#define AKV_HALVES  (ABKV * HSTR) // 4608
#define ATT_SMEM_B  ((AQ_HALVES + 4 * AKV_HALVES) * 2)  // 55296 B

__global__ __launch_bounds__(256, 2) void attn_fp16(
    const __half* __restrict__ Qh, const __half* __restrict__ Kh,
    const __half* __restrict__ Vth, float* __restrict__ Ctx)
{
    extern __shared__ __half hsm[];
    __half* Qs  = hsm;                          // [128][72]
    __half* Ks  = Qs + AQ_HALVES;               // 2 x [64][72]
    __half* Vts = Ks + 2 * AKV_HALVES;          // 2 x [64][72] (d-major)
    const uint32_t ks_base  = smem_u32(Ks);
    const uint32_t vts_base = smem_u32(Vts);

    const int tid  = threadIdx.x;
    const int wid  = tid >> 5;
    const int lane = tid & 31;
    const int g    = lane >> 2;
    const int tg   = lane & 3;
    const int wm   = wid * 16;
    const int qt   = blockIdx.x;
    const int h    = blockIdx.y;
    const int b    = blockIdx.z;
    const float SC2 = 0.125f * 1.44269504f;   // scale * log2(e)

    const __half* Qg = Qh + ((size_t)(b * LQ + qt * 128)) * DMODEL + h * HDIM;
    const __half* Kg = Kh + ((size_t)(b * LK)) * DMODEL + h * HDIM;
    const __half* Vg = Vth + ((size_t)((b * NHEAD + h) * HDIM)) * LK;

    // ---- load Q tile into smem (once) ----
#pragma unroll
    for (int it = 0; it < 16; it++) {
        int idx = it * 256 + tid;            // 0..4095
        int row = idx >> 5, c2 = idx & 31;
        __half2 v = ((const __half2*)(Qg + (size_t)row * DMODEL))[c2];
        *(__half2*)&Qs[row * HSTR + c2 * 2] = v;
    }

    // ---- KV tile loader (stage s) ----
    auto load_kv = [&](int t, int s) {
#pragma unroll
        for (int i = 0; i < 4; i++) {
            int idx = i * 256 + tid;         // 0..1023
            if (idx < 512) {
                int row = idx >> 3, ch = idx & 7;          // K: 64 rows x 8 chunks
                cp_async16(ks_base + (s * AKV_HALVES + row * HSTR + ch * 8) * 2,
                           Kg + (size_t)(t * ABKV + row) * DMODEL + ch * 8);
            } else {
                int j = idx - 512;
                int d = j >> 3, ch = j & 7;                // Vt: 64 d-rows x 8 chunks
                cp_async16(vts_base + (s * AKV_HALVES + d * HSTR + ch * 8) * 2,
                           Vg + (size_t)d * LK + t * ABKV + ch * 8);
            }
        }
    };

    load_kv(0, 0); CP_COMMIT();
    __syncthreads();   // Q smem visible

    // ---- hoist Q fragments to registers ----
    uint32_t qf[4][4];
#pragma unroll
    for (int ks = 0; ks < 4; ks++) {
        int c = ks * 16 + 2 * tg;
        qf[ks][0] = *(const uint32_t*)&Qs[(wm + g) * HSTR + c];
        qf[ks][1] = *(const uint32_t*)&Qs[(wm + g + 8) * HSTR + c];
        qf[ks][2] = *(const uint32_t*)&Qs[(wm + g) * HSTR + c + 8];
        qf[ks][3] = *(const uint32_t*)&Qs[(wm + g + 8) * HSTR + c + 8];
    }

    float o[8][4];
#pragma unroll
    for (int nd = 0; nd < 8; nd++)
#pragma unroll
        for (int r = 0; r < 4; r++) o[nd][r] = 0.f;
    float m0 = -1e30f, m1 = -1e30f, l0 = 0.f, l1 = 0.f;

    for (int t = 0; t < ANT; t++) {
        const int s = t & 1;
        if (t + 1 < ANT) load_kv(t + 1, (t + 1) & 1);
        CP_COMMIT();
        CP_WAIT(1);
        __syncthreads();

        const __half* ksm = Ks + s * AKV_HALVES;
        const __half* vsm = Vts + s * AKV_HALVES;

        // ---- S = Q K^T (8 n-blocks of 8 kv) ----
        float sc[8][4];
#pragma unroll
        for (int nb = 0; nb < 8; nb++)
#pragma unroll
            for (int r = 0; r < 4; r++) sc[nb][r] = 0.f;
#pragma unroll
        for (int ks = 0; ks < 4; ks++) {
            int c = ks * 16 + 2 * tg;
#pragma unroll
            for (int nb = 0; nb < 8; nb++) {
                uint32_t b0 = *(const uint32_t*)&ksm[(nb * 8 + g) * HSTR + c];
                uint32_t b1 = *(const uint32_t*)&ksm[(nb * 8 + g) * HSTR + c + 8];
                mma_f16(sc[nb], qf[ks], b0, b1);
            }
        }

        // ---- online softmax (rows g and g+8) ----
        float rmax0 = -1e30f, rmax1 = -1e30f;
#pragma unroll
        for (int nb = 0; nb < 8; nb++) {
            rmax0 = fmaxf(rmax0, fmaxf(sc[nb][0], sc[nb][1]));
            rmax1 = fmaxf(rmax1, fmaxf(sc[nb][2], sc[nb][3]));
        }
        rmax0 = fmaxf(rmax0, __shfl_xor_sync(0xffffffff, rmax0, 1));
        rmax0 = fmaxf(rmax0, __shfl_xor_sync(0xffffffff, rmax0, 2));
        rmax1 = fmaxf(rmax1, __shfl_xor_sync(0xffffffff, rmax1, 1));
        rmax1 = fmaxf(rmax1, __shfl_xor_sync(0xffffffff, rmax1, 2));

        float mn0 = fmaxf(m0, rmax0), mn1 = fmaxf(m1, rmax1);
        float cr0 = exp2f((m0 - mn0) * SC2), cr1 = exp2f((m1 - mn1) * SC2);
        m0 = mn0; m1 = mn1;

        uint32_t phA[8], phB[8];
        float sum0 = 0.f, sum1 = 0.f;
#pragma unroll
        for (int nb = 0; nb < 8; nb++) {
            float p0 = exp2f((sc[nb][0] - mn0) * SC2);
            float p1 = exp2f((sc[nb][1] - mn0) * SC2);
            float p2 = exp2f((sc[nb][2] - mn1) * SC2);
            float p3 = exp2f((sc[nb][3] - mn1) * SC2);
            sum0 += p0 + p1;
            sum1 += p2 + p3;
            phA[nb] = pack_h2(p0, p1);
            phB[nb] = pack_h2(p2, p3);
        }
        sum0 += __shfl_xor_sync(0xffffffff, sum0, 1);
        sum0 += __shfl_xor_sync(0xffffffff, sum0, 2);
        sum1 += __shfl_xor_sync(0xffffffff, sum1, 1);
        sum1 += __shfl_xor_sync(0xffffffff, sum1, 2);
        l0 = l0 * cr0 + sum0;
        l1 = l1 * cr1 + sum1;

        // ---- rescale O, then O += P V ----
#pragma unroll
        for (int nd = 0; nd < 8; nd++) {
            o[nd][0] *= cr0; o[nd][1] *= cr0;
            o[nd][2] *= cr1; o[nd][3] *= cr1;
        }
#pragma unroll
        for (int j = 0; j < 4; j++) {          // kv k16 steps
            uint32_t a[4] = { phA[2 * j], phB[2 * j], phA[2 * j + 1], phB[2 * j + 1] };
            int c = j * 16 + 2 * tg;
#pragma unroll
            for (int nd = 0; nd < 8; nd++) {
                uint32_t b0 = *(const uint32_t*)&vsm[(nd * 8 + g) * HSTR + c];
                uint32_t b1 = *(const uint32_t*)&vsm[(nd * 8 + g) * HSTR + c + 8];
                mma_f16(o[nd], a, b0, b1);
            }
        }
        __syncthreads();
    }

    // ---- epilogue: O / l, tf32-rounded to ctx ----
    const float inv0 = 1.f / l0, inv1 = 1.f / l1;
    const int row0 = b * LQ + qt * 128 + wm + g;
#pragma unroll
    for (int nd = 0; nd < 8; nd++) {
        const int col = h * HDIM + nd * 8 + 2 * tg;
        float2 a0 = { round_tf32(o[nd][0] * inv0), round_tf32(o[nd][1] * inv0) };
        float2 a1 = { round_tf32(o[nd][2] * inv1), round_tf32(o[nd][3] * inv1) };
        *(float2*)(Ctx + (size_t)row0 * DMODEL + col) = a0;
        *(float2*)(Ctx + (size_t)(row0 + 8) * DMODEL + col) = a1;
    }
}

// ---------------------------------------------------------------------------
// Launch
// ---------------------------------------------------------------------------
extern "C" void kernel_launch(void* const* d_in, const int* in_sizes, int n_in,
                              void* d_out, int out_size)
{
    const float* X   = (const float*)d_in[0];
    const float* Y   = (const float*)d_in[1];
    const float* Wq  = (const float*)d_in[2];
    const float* bq  = (const float*)d_in[3];
    const float* Wkv = (const float*)d_in[4];
    const float* bkv = (const float*)d_in[5];
    const float* Wo  = (const float*)d_in[6];
    const float* bo  = (const float*)d_in[7];
    float* out = (float*)d_out;

    void *pxr, *pyr, *pwq, *pwkv, *pwo, *pqh, *pkh, *pvth, *pctx;
    cudaGetSymbolAddress(&pxr,  g_xr);
    cudaGetSymbolAddress(&pyr,  g_yr);
    cudaGetSymbolAddress(&pwq,  g_wqr);
    cudaGetSymbolAddress(&pwkv, g_wkvr);
    cudaGetSymbolAddress(&pwo,  g_wor);
    cudaGetSymbolAddress(&pqh,  g_qh);
    cudaGetSymbolAddress(&pkh,  g_kh);
    cudaGetSymbolAddress(&pvth, g_vth);
    cudaGetSymbolAddress(&pctx, g_ctx);
    float*  xr   = (float*)pxr;    float*  yr   = (float*)pyr;
    float*  wqr  = (float*)pwq;    float*  wkvr = (float*)pwkv;
    float*  wor  = (float*)pwo;
    __half* qh   = (__half*)pqh;   __half* kh   = (__half*)pkh;
    __half* vth  = (__half*)pvth;
    float*  ctx_s = (float*)pctx;

    cudaFuncSetAttribute(gemm_tf32, cudaFuncAttributeMaxDynamicSharedMemorySize,
                         GEMM_SMEM);
    cudaFuncSetAttribute(attn_fp16, cudaFuncAttributeMaxDynamicSharedMemorySize,
                         ATT_SMEM_B);

    const int M = BATCH * LQ;

    auto cvt = [&](const float* in, float* o, int n) {
        int n4 = n / 4;
        cvt_tf32_kernel<<<(n4 + 255) / 256, 256>>>(in, o, n4);
    };
    cvt(X,   xr,   M * DMODEL);
    cvt(Y,   yr,   M * DMODEL);
    cvt(Wq,  wqr,  DMODEL * DMODEL);
    cvt(Wkv, wkvr, 2 * DMODEL * DMODEL);
    cvt(Wo,  wor,  DMODEL * DMODEL);

    // 1) Q projection -> fp16 Qh
    gemm_tf32<<<dim3(DMODEL / BN, M / BM), 256, GEMM_SMEM>>>(
        xr, wqr, bq, nullptr, qh, nullptr, M, DMODEL, DMODEL, 1);
    // 2) KV projection -> fp16 Kh + transposed Vth
    gemm_tf32<<<dim3(2 * DMODEL / BN, M / BM), 256, GEMM_SMEM>>>(
        yr, wkvr, bkv, nullptr, kh, vth, M, 2 * DMODEL, DMODEL, 2);
    // 3) fp16 tensor-core flash attention -> tf32-rounded ctx
    attn_fp16<<<dim3(LQ / 128, NHEAD, BATCH), 256, ATT_SMEM_B>>>(
        qh, kh, vth, ctx_s);
    // 4) Output projection -> fp32 out
    gemm_tf32<<<dim3(DMODEL / BN, M / BM), 256, GEMM_SMEM>>>(
        ctx_s, wor, bo, out, nullptr, nullptr, M, DMODEL, DMODEL, 0);
}

// round 5
// speedup vs baseline: 5.7710x; 1.5522x over previous
#include <cuda_runtime.h>
#include <cuda_fp16.h>
#include <cuda_bf16.h>
#include <cstdint>
#include <cstddef>
#include <math.h>

// ---------------------------------------------------------------------------
// BartCrossAttention: B=4, LQ=LK=1024, D=1024, H=16, HD=64, fp32 in/out
// Round 5: fp16 m16n8k16 mma for projections AND attention (fp32 accumulate).
// ---------------------------------------------------------------------------

#define BATCH 4
#define LQ    1024
#define LK    1024
#define DMODEL 1024
#define NHEAD 16
#define HDIM  64

// Scratch (__device__ globals; no allocations allowed)
__device__ __half g_xh  [(size_t)BATCH * LQ * DMODEL];
__device__ __half g_yh  [(size_t)BATCH * LK * DMODEL];
__device__ __half g_wqh [(size_t)DMODEL * DMODEL];
__device__ __half g_wkvh[(size_t)2 * DMODEL * DMODEL];
__device__ __half g_woh [(size_t)DMODEL * DMODEL];
__device__ __half g_qh  [(size_t)BATCH * LQ * DMODEL];            // Q fp16
__device__ __half g_kh  [(size_t)BATCH * LK * DMODEL];            // K fp16 [tok][h*64+d]
__device__ __half g_vth [(size_t)BATCH * NHEAD * HDIM * LK];      // V^T fp16 [(b,h,d)][tok]
__device__ __half g_ctxh[(size_t)BATCH * LQ * DMODEL];            // ctx fp16

// ---------------------------------------------------------------------------
// helpers
// ---------------------------------------------------------------------------
__device__ __forceinline__ uint32_t smem_u32(const void* p) {
    uint32_t a;
    asm("{ .reg .u64 t; cvta.to.shared.u64 t, %1; cvt.u32.u64 %0, t; }"
        : "=r"(a) : "l"(p));
    return a;
}

// m16n8k16 fp16 mma, fp32 accumulate
__device__ __forceinline__ void mma_f16(float* c, const uint32_t* a, uint32_t b0, uint32_t b1) {
    asm volatile(
        "mma.sync.aligned.m16n8k16.row.col.f32.f16.f16.f32 "
        "{%0,%1,%2,%3}, {%4,%5,%6,%7}, {%8,%9}, {%0,%1,%2,%3};"
        : "+f"(c[0]), "+f"(c[1]), "+f"(c[2]), "+f"(c[3])
        : "r"(a[0]), "r"(a[1]), "r"(a[2]), "r"(a[3]), "r"(b0), "r"(b1));
}

__device__ __forceinline__ void cp_async16(uint32_t dst, const void* src) {
    asm volatile("cp.async.cg.shared.global [%0], [%1], 16;"
                 :: "r"(dst), "l"(src));
}
#define CP_COMMIT()  asm volatile("cp.async.commit_group;" ::: "memory")
#define CP_WAIT(n)   asm volatile("cp.async.wait_group %0;" :: "n"(n) : "memory")

__device__ __forceinline__ uint32_t pack_h2(float lo, float hi) {
    __half2 h = __floats2half2_rn(lo, hi);
    return *reinterpret_cast<uint32_t*>(&h);
}

// ---------------------------------------------------------------------------
// fp16 tensor-core GEMM: C[M,N] = A[M,K] @ W[N,K]^T + bias[N]
// Block 128x128, 8 warps (2x4), warp tile 64x32, BK=64 halves, 3-stage cp.async.
// smem stride 72 halves -> fragment LDS bank = (4g+tg+const): conflict-free.
// mode 0: fp32 C.  mode 1: fp16 Hout.  mode 2: KV split (K->Hout, V->Vth^T).
// ---------------------------------------------------------------------------
#define BM 128
#define BN 128
#define BKH 64                                 // halves per k-chunk (128 B/row)
#define GSTAGES 3
#define HSTR2 72                               // smem row stride in halves
#define STG_HALVES ((BM + BN) * HSTR2)         // 18432
#define STG_B  (STG_HALVES * 2)                // 36864 B
#define GEMM_SMEM (GSTAGES * STG_B)            // 110592 B

__global__ __launch_bounds__(256, 2) void gemm_f16(
    const __half* __restrict__ A, const __half* __restrict__ W,
    const float* __restrict__ bias, float* __restrict__ C,
    __half* __restrict__ Hout, __half* __restrict__ Vth,
    int M, int N, int K, int mode)
{
    extern __shared__ __half smh[];
    const uint32_t sbase = smem_u32(smh);

    const int tid  = threadIdx.x;
    const int wid  = tid >> 5;
    const int lane = tid & 31;
    const int g    = lane >> 2;
    const int tg   = lane & 3;
    const int wm   = (wid & 1) * 64;
    const int wn   = (wid >> 1) * 32;
    const int m0   = blockIdx.y * BM;
    const int n0   = blockIdx.x * BN;

    // 2048 x 16B chunks per stage (A:1024, B:1024), 8 per thread
    auto load_stage = [&](int chunk, int s) {
        const int k0 = chunk * BKH;
        const uint32_t stA = sbase + s * STG_B;
        const uint32_t stB = stA + BM * HSTR2 * 2;
#pragma unroll
        for (int i = 0; i < 8; i++) {
            int idx = i * 256 + tid;
            if (idx < 1024) {
                int row = idx >> 3, ch = idx & 7;
                cp_async16(stA + (row * HSTR2 + ch * 8) * 2,
                           A + (size_t)(m0 + row) * K + k0 + ch * 8);
            } else {
                int j = idx - 1024;
                int row = j >> 3, ch = j & 7;
                cp_async16(stB + (row * HSTR2 + ch * 8) * 2,
                           W + (size_t)(n0 + row) * K + k0 + ch * 8);
            }
        }
    };

    float acc[4][4][4];
#pragma unroll
    for (int mi = 0; mi < 4; mi++)
#pragma unroll
        for (int ni = 0; ni < 4; ni++)
#pragma unroll
            for (int r = 0; r < 4; r++) acc[mi][ni][r] = 0.f;

    const int nchunks = K / BKH;  // 16
    load_stage(0, 0); CP_COMMIT();
    load_stage(1, 1); CP_COMMIT();

    for (int k = 0; k < nchunks; k++) {
        const int s = k % GSTAGES;
        if (k + 2 < nchunks) load_stage(k + 2, (k + 2) % GSTAGES);
        CP_COMMIT();
        CP_WAIT(2);
        __syncthreads();

        const __half* as = smh + s * STG_HALVES;
        const __half* bs = as + BM * HSTR2;

#pragma unroll
        for (int ks = 0; ks < BKH / 16; ks++) {   // 4 k16 steps
            const int c = ks * 16 + 2 * tg;
            uint32_t af[4][4];
#pragma unroll
            for (int mi = 0; mi < 4; mi++) {
                const __half* p = as + (wm + mi * 16 + g) * HSTR2 + c;
                af[mi][0] = *(const uint32_t*)(p);
                af[mi][1] = *(const uint32_t*)(p + 8 * HSTR2);
                af[mi][2] = *(const uint32_t*)(p + 8);
                af[mi][3] = *(const uint32_t*)(p + 8 * HSTR2 + 8);
            }
            uint32_t bf[4][2];
#pragma unroll
            for (int ni = 0; ni < 4; ni++) {
                const __half* p = bs + (wn + ni * 8 + g) * HSTR2 + c;
                bf[ni][0] = *(const uint32_t*)(p);
                bf[ni][1] = *(const uint32_t*)(p + 8);
            }
#pragma unroll
            for (int mi = 0; mi < 4; mi++)
#pragma unroll
                for (int ni = 0; ni < 4; ni++)
                    mma_f16(acc[mi][ni], af[mi], bf[ni][0], bf[ni][1]);
        }
        __syncthreads();
    }

    // epilogue
#pragma unroll
    for (int ni = 0; ni < 4; ni++) {
        const int col = n0 + wn + ni * 8 + 2 * tg;
        const float2 bv = *(const float2*)(bias + col);
#pragma unroll
        for (int mi = 0; mi < 4; mi++) {
            const int r0 = m0 + wm + mi * 16 + g;
            float v00 = acc[mi][ni][0] + bv.x, v01 = acc[mi][ni][1] + bv.y;
            float v10 = acc[mi][ni][2] + bv.x, v11 = acc[mi][ni][3] + bv.y;
            if (mode == 0) {
                float2 a0 = { v00, v01 }, a1 = { v10, v11 };
                *(float2*)(C + (size_t)r0 * N + col) = a0;
                *(float2*)(C + (size_t)(r0 + 8) * N + col) = a1;
            } else if (mode == 1) {
                *(__half2*)(Hout + (size_t)r0 * N + col) = __floats2half2_rn(v00, v01);
                *(__half2*)(Hout + (size_t)(r0 + 8) * N + col) = __floats2half2_rn(v10, v11);
            } else {
                const int h = col >> 7, w = col & 127;
                const int b = r0 >> 10;
                const int tok = r0 & 1023;
                if (w < 64) {
                    *(__half2*)(Hout + (size_t)r0 * DMODEL + h * 64 + w) =
                        __floats2half2_rn(v00, v01);
                    *(__half2*)(Hout + (size_t)(r0 + 8) * DMODEL + h * 64 + w) =
                        __floats2half2_rn(v10, v11);
                } else {
                    const int d = w - 64;
                    __half* vr0 = Vth + ((size_t)((b * NHEAD + h) * HDIM + d)) * LK;
                    __half* vr1 = Vth + ((size_t)((b * NHEAD + h) * HDIM + d + 1)) * LK;
                    vr0[tok]     = __float2half_rn(v00);
                    vr1[tok]     = __float2half_rn(v01);
                    vr0[tok + 8] = __float2half_rn(v10);
                    vr1[tok + 8] = __float2half_rn(v11);
                }
            }
        }
    }
}

// ---------------------------------------------------------------------------
// fp32 -> fp16 convert (float4 in, 4 halves out)
// ---------------------------------------------------------------------------
__global__ __launch_bounds__(256) void cvt_f16_kernel(
    const float* __restrict__ in, __half* __restrict__ out, int n4)
{
    int i = blockIdx.x * blockDim.x + threadIdx.x;
    if (i < n4) {
        float4 v = ((const float4*)in)[i];
        __half2 h0 = __floats2half2_rn(v.x, v.y);
        __half2 h1 = __floats2half2_rn(v.z, v.w);
        ((__half2*)out)[2 * i]     = h0;
        ((__half2*)out)[2 * i + 1] = h1;
    }
}

// ---------------------------------------------------------------------------
// fp16 tensor-core flash attention (unchanged from R4 except fp16 ctx out).
// ---------------------------------------------------------------------------
#define ABKV 64
#define ANT  (LK / ABKV)
#define HSTR 72
#define AQ_HALVES   (128 * HSTR)
#define AKV_HALVES  (ABKV * HSTR)
#define ATT_SMEM_B  ((AQ_HALVES + 4 * AKV_HALVES) * 2)

__global__ __launch_bounds__(256, 2) void attn_fp16(
    const __half* __restrict__ Qh, const __half* __restrict__ Kh,
    const __half* __restrict__ Vth, __half* __restrict__ Ctx)
{
    extern __shared__ __half hsm[];
    __half* Qs  = hsm;
    __half* Ks  = Qs + AQ_HALVES;
    __half* Vts = Ks + 2 * AKV_HALVES;
    const uint32_t ks_base  = smem_u32(Ks);
    const uint32_t vts_base = smem_u32(Vts);

    const int tid  = threadIdx.x;
    const int wid  = tid >> 5;
    const int lane = tid & 31;
    const int g    = lane >> 2;
    const int tg   = lane & 3;
    const int wm   = wid * 16;
    const int qt   = blockIdx.x;
    const int h    = blockIdx.y;
    const int b    = blockIdx.z;
    const float SC2 = 0.125f * 1.44269504f;

    const __half* Qg = Qh + ((size_t)(b * LQ + qt * 128)) * DMODEL + h * HDIM;
    const __half* Kg = Kh + ((size_t)(b * LK)) * DMODEL + h * HDIM;
    const __half* Vg = Vth + ((size_t)((b * NHEAD + h) * HDIM)) * LK;

#pragma unroll
    for (int it = 0; it < 16; it++) {
        int idx = it * 256 + tid;
        int row = idx >> 5, c2 = idx & 31;
        __half2 v = ((const __half2*)(Qg + (size_t)row * DMODEL))[c2];
        *(__half2*)&Qs[row * HSTR + c2 * 2] = v;
    }

    auto load_kv = [&](int t, int s) {
#pragma unroll
        for (int i = 0; i < 4; i++) {
            int idx = i * 256 + tid;
            if (idx < 512) {
                int row = idx >> 3, ch = idx & 7;
                cp_async16(ks_base + (s * AKV_HALVES + row * HSTR + ch * 8) * 2,
                           Kg + (size_t)(t * ABKV + row) * DMODEL + ch * 8);
            } else {
                int j = idx - 512;
                int d = j >> 3, ch = j & 7;
                cp_async16(vts_base + (s * AKV_HALVES + d * HSTR + ch * 8) * 2,
                           Vg + (size_t)d * LK + t * ABKV + ch * 8);
            }
        }
    };

    load_kv(0, 0); CP_COMMIT();
    __syncthreads();

    uint32_t qf[4][4];
#pragma unroll
    for (int ks = 0; ks < 4; ks++) {
        int c = ks * 16 + 2 * tg;
        qf[ks][0] = *(const uint32_t*)&Qs[(wm + g) * HSTR + c];
        qf[ks][1] = *(const uint32_t*)&Qs[(wm + g + 8) * HSTR + c];
        qf[ks][2] = *(const uint32_t*)&Qs[(wm + g) * HSTR + c + 8];
        qf[ks][3] = *(const uint32_t*)&Qs[(wm + g + 8) * HSTR + c + 8];
    }

    float o[8][4];
#pragma unroll
    for (int nd = 0; nd < 8; nd++)
#pragma unroll
        for (int r = 0; r < 4; r++) o[nd][r] = 0.f;
    float m0 = -1e30f, m1 = -1e30f, l0 = 0.f, l1 = 0.f;

    for (int t = 0; t < ANT; t++) {
        const int s = t & 1;
        if (t + 1 < ANT) load_kv(t + 1, (t + 1) & 1);
        CP_COMMIT();
        CP_WAIT(1);
        __syncthreads();

        const __half* ksm = Ks + s * AKV_HALVES;
        const __half* vsm = Vts + s * AKV_HALVES;

        float sc[8][4];
#pragma unroll
        for (int nb = 0; nb < 8; nb++)
#pragma unroll
            for (int r = 0; r < 4; r++) sc[nb][r] = 0.f;
#pragma unroll
        for (int ks = 0; ks < 4; ks++) {
            int c = ks * 16 + 2 * tg;
#pragma unroll
            for (int nb = 0; nb < 8; nb++) {
                uint32_t b0 = *(const uint32_t*)&ksm[(nb * 8 + g) * HSTR + c];
                uint32_t b1 = *(const uint32_t*)&ksm[(nb * 8 + g) * HSTR + c + 8];
                mma_f16(sc[nb], qf[ks], b0, b1);
            }
        }

        float rmax0 = -1e30f, rmax1 = -1e30f;
#pragma unroll
        for (int nb = 0; nb < 8; nb++) {
            rmax0 = fmaxf(rmax0, fmaxf(sc[nb][0], sc[nb][1]));
            rmax1 = fmaxf(rmax1, fmaxf(sc[nb][2], sc[nb][3]));
        }
        rmax0 = fmaxf(rmax0, __shfl_xor_sync(0xffffffff, rmax0, 1));
        rmax0 = fmaxf(rmax0, __shfl_xor_sync(0xffffffff, rmax0, 2));
        rmax1 = fmaxf(rmax1, __shfl_xor_sync(0xffffffff, rmax1, 1));
        rmax1 = fmaxf(rmax1, __shfl_xor_sync(0xffffffff, rmax1, 2));

        float mn0 = fmaxf(m0, rmax0), mn1 = fmaxf(m1, rmax1);
        float cr0 = exp2f((m0 - mn0) * SC2), cr1 = exp2f((m1 - mn1) * SC2);
        m0 = mn0; m1 = mn1;

        uint32_t phA[8], phB[8];
        float sum0 = 0.f, sum1 = 0.f;
#pragma unroll
        for (int nb = 0; nb < 8; nb++) {
            float p0 = exp2f((sc[nb][0] - mn0) * SC2);
            float p1 = exp2f((sc[nb][1] - mn0) * SC2);
            float p2 = exp2f((sc[nb][2] - mn1) * SC2);
            float p3 = exp2f((sc[nb][3] - mn1) * SC2);
            sum0 += p0 + p1;
            sum1 += p2 + p3;
            phA[nb] = pack_h2(p0, p1);
            phB[nb] = pack_h2(p2, p3);
        }
        sum0 += __shfl_xor_sync(0xffffffff, sum0, 1);
        sum0 += __shfl_xor_sync(0xffffffff, sum0, 2);
        sum1 += __shfl_xor_sync(0xffffffff, sum1, 1);
        sum1 += __shfl_xor_sync(0xffffffff, sum1, 2);
        l0 = l0 * cr0 + sum0;
        l1 = l1 * cr1 + sum1;

#pragma unroll
        for (int nd = 0; nd < 8; nd++) {
            o[nd][0] *= cr0; o[nd][1] *= cr0;
            o[nd][2] *= cr1; o[nd][3] *= cr1;
        }
#pragma unroll
        for (int j = 0; j < 4; j++) {
            uint32_t a[4] = { phA[2 * j], phB[2 * j], phA[2 * j + 1], phB[2 * j + 1] };
            int c = j * 16 + 2 * tg;
#pragma unroll
            for (int nd = 0; nd < 8; nd++) {
                uint32_t b0 = *(const uint32_t*)&vsm[(nd * 8 + g) * HSTR + c];
                uint32_t b1 = *(const uint32_t*)&vsm[(nd * 8 + g) * HSTR + c + 8];
                mma_f16(o[nd], a, b0, b1);
            }
        }
        __syncthreads();
    }

    const float inv0 = 1.f / l0, inv1 = 1.f / l1;
    const int row0 = b * LQ + qt * 128 + wm + g;
#pragma unroll
    for (int nd = 0; nd < 8; nd++) {
        const int col = h * HDIM + nd * 8 + 2 * tg;
        *(__half2*)(Ctx + (size_t)row0 * DMODEL + col) =
            __floats2half2_rn(o[nd][0] * inv0, o[nd][1] * inv0);
        *(__half2*)(Ctx + (size_t)(row0 + 8) * DMODEL + col) =
            __floats2half2_rn(o[nd][2] * inv1, o[nd][3] * inv1);
    }
}

// ---------------------------------------------------------------------------
// Launch
// ---------------------------------------------------------------------------
extern "C" void kernel_launch(void* const* d_in, const int* in_sizes, int n_in,
                              void* d_out, int out_size)
{
    const float* X   = (const float*)d_in[0];
    const float* Y   = (const float*)d_in[1];
    const float* Wq  = (const float*)d_in[2];
    const float* bq  = (const float*)d_in[3];
    const float* Wkv = (const float*)d_in[4];
    const float* bkv = (const float*)d_in[5];
    const float* Wo  = (const float*)d_in[6];
    const float* bo  = (const float*)d_in[7];
    float* out = (float*)d_out;

    void *pxh, *pyh, *pwq, *pwkv, *pwo, *pqh, *pkh, *pvth, *pctx;
    cudaGetSymbolAddress(&pxh,  g_xh);
    cudaGetSymbolAddress(&pyh,  g_yh);
    cudaGetSymbolAddress(&pwq,  g_wqh);
    cudaGetSymbolAddress(&pwkv, g_wkvh);
    cudaGetSymbolAddress(&pwo,  g_woh);
    cudaGetSymbolAddress(&pqh,  g_qh);
    cudaGetSymbolAddress(&pkh,  g_kh);
    cudaGetSymbolAddress(&pvth, g_vth);
    cudaGetSymbolAddress(&pctx, g_ctxh);
    __half* xh   = (__half*)pxh;   __half* yh   = (__half*)pyh;
    __half* wqh  = (__half*)pwq;   __half* wkvh = (__half*)pwkv;
    __half* woh  = (__half*)pwo;
    __half* qh   = (__half*)pqh;   __half* kh   = (__half*)pkh;
    __half* vth  = (__half*)pvth;  __half* ctxh = (__half*)pctx;

    cudaFuncSetAttribute(gemm_f16, cudaFuncAttributeMaxDynamicSharedMemorySize,
                         GEMM_SMEM);
    cudaFuncSetAttribute(attn_fp16, cudaFuncAttributeMaxDynamicSharedMemorySize,
                         ATT_SMEM_B);

    const int M = BATCH * LQ;

    auto cvt = [&](const float* in, __half* o, int n) {
        int n4 = n / 4;
        cvt_f16_kernel<<<(n4 + 255) / 256, 256>>>(in, o, n4);
    };
    cvt(X,   xh,   M * DMODEL);
    cvt(Y,   yh,   M * DMODEL);
    cvt(Wq,  wqh,  DMODEL * DMODEL);
    cvt(Wkv, wkvh, 2 * DMODEL * DMODEL);
    cvt(Wo,  woh,  DMODEL * DMODEL);

    // 1) Q projection -> fp16 Qh
    gemm_f16<<<dim3(DMODEL / BN, M / BM), 256, GEMM_SMEM>>>(
        xh, wqh, bq, nullptr, qh, nullptr, M, DMODEL, DMODEL, 1);
    // 2) KV projection -> fp16 Kh + transposed Vth
    gemm_f16<<<dim3(2 * DMODEL / BN, M / BM), 256, GEMM_SMEM>>>(
        yh, wkvh, bkv, nullptr, kh, vth, M, 2 * DMODEL, DMODEL, 2);
    // 3) fp16 flash attention -> fp16 ctx
    attn_fp16<<<dim3(LQ / 128, NHEAD, BATCH), 256, ATT_SMEM_B>>>(
        qh, kh, vth, ctxh);
    // 4) Output projection -> fp32 out
    gemm_f16<<<dim3(DMODEL / BN, M / BM), 256, GEMM_SMEM>>>(
        ctxh, woh, bo, out, nullptr, nullptr, M, DMODEL, DMODEL, 0);
}